// round 7
// baseline (speedup 1.0000x reference)
#include <cuda_runtime.h>

#define B_SZ 4
#define C_DIM 256
#define L_DIM 4096
#define N_GROUPS 32
#define C_PG 8          // C_DIM / N_GROUPS

#define CL (C_DIM * L_DIM)          // 1,048,576  per-batch stride for [C,L] tensors
#define LL (L_DIM * L_DIM)          // 16,777,216 per-batch stride for scores

// ---------------- scratch (device globals; no allocation allowed) ----------------
__device__ float g_h [B_SZ * CL];   // normalized input
__device__ float g_q [B_SZ * CL];
__device__ float g_k [B_SZ * CL];
__device__ float g_v [B_SZ * CL];
__device__ float g_h2[B_SZ * CL];   // attention output
__device__ float g_s [B_SZ * LL];   // scores / probs (256 MB)

// ---------------- f32x2 helpers (Blackwell packed fp32, 2x FFMA rate) ----------------
__device__ __forceinline__ unsigned long long pack2(float v) {
    unsigned long long r;
    unsigned int u = __float_as_uint(v);
    asm("mov.b64 %0, {%1, %2};" : "=l"(r) : "r"(u), "r"(u));
    return r;
}
__device__ __forceinline__ void ffma2(unsigned long long& d,
                                      unsigned long long a,
                                      unsigned long long b) {
    asm("fma.rn.f32x2 %0, %1, %2, %0;" : "+l"(d) : "l"(a), "l"(b));
}

// ---------------- GroupNorm ----------------
__global__ void gn_kernel(const float* __restrict__ x,
                          const float* __restrict__ gamma,
                          const float* __restrict__ beta) {
    int b = blockIdx.x / N_GROUPS;
    int g = blockIdx.x % N_GROUPS;
    const int N = C_PG * L_DIM;                       // 32768
    size_t base = ((size_t)b * C_DIM + g * C_PG) * L_DIM;
    const float* xp = x + base;
    float* hp = g_h + base;
    int t = threadIdx.x;

    float s = 0.f, ss = 0.f;
    for (int i = t; i < N; i += 256) {
        float v = xp[i];
        s += v;
        ss = fmaf(v, v, ss);
    }
    #pragma unroll
    for (int o = 16; o; o >>= 1) {
        s  += __shfl_xor_sync(0xffffffffu, s,  o);
        ss += __shfl_xor_sync(0xffffffffu, ss, o);
    }
    __shared__ float shs[8], shss[8];
    if ((t & 31) == 0) { shs[t >> 5] = s; shss[t >> 5] = ss; }
    __syncthreads();
    float ts = 0.f, tss = 0.f;
    #pragma unroll
    for (int w = 0; w < 8; w++) { ts += shs[w]; tss += shss[w]; }

    float mean = ts / (float)N;
    float var  = tss / (float)N - mean * mean;
    float rstd = rsqrtf(var + 1e-6f);

    for (int i = t; i < N; i += 256) {
        int c = g * C_PG + (i >> 12);                 // i / L_DIM
        hp[i] = (xp[i] - mean) * rstd * gamma[c] + beta[c];
    }
}

// ---------------- generic SGEMM:  C[m,n] = alpha * sum_k Ahat[k,m]*Bhat[k,n] (+bias[m]) (+res) ----
// TRA=0: A is [K x M] row-major (Ahat[k,m] = A[k*lda+m])
// TRA=1: A is [M x K] row-major (Ahat[k,m] = A[m*lda+k])    (same for B with n)
#define BM 128
#define BN 128
#define BK 16
#define SROW 132

template<int TRA, int TRB, bool BIAS, bool RES>
__global__ __launch_bounds__(256, 2)
void gemm_kernel(const float* __restrict__ Ab, const float* __restrict__ Bb,
                 const float* __restrict__ bias, const float* __restrict__ Rb,
                 float* __restrict__ Cb,
                 int K, int lda, int ldb, int ldc, float alpha,
                 long sA, long sB, long sR, long sC) {
    const float* A = Ab + (long)blockIdx.z * sA;
    const float* B = Bb + (long)blockIdx.z * sB;
    float* C       = Cb + (long)blockIdx.z * sC;

    int m0 = blockIdx.y * BM;
    int n0 = blockIdx.x * BN;

    __shared__ __align__(16) float As[BK][SROW];
    __shared__ __align__(16) float Bs[BK][SROW];

    int t = threadIdx.x;
    int warp = t >> 5, lane = t & 31;
    int wm = warp >> 1, wn = warp & 1;
    int lm = lane >> 3, ln = lane & 7;
    int mb = wm * 32 + lm * 4;    // rows mb..mb+3 and mb+16..mb+19
    int nb = wn * 64 + ln * 4;    // cols nb..nb+3 and nb+32..nb+35

    unsigned long long acc[8][4];
    #pragma unroll
    for (int i = 0; i < 8; i++)
        #pragma unroll
        for (int j = 0; j < 4; j++) acc[i][j] = 0ull;

    for (int k0 = 0; k0 < K; k0 += BK) {
        // ---- load A tile into As[k][m]
        if (TRA == 0) {
            int ak = t >> 5;
            int am = (t & 31) * 4;
            #pragma unroll
            for (int r = 0; r < 2; r++) {
                int kk = ak + r * 8;
                float4 v = *reinterpret_cast<const float4*>(A + (long)(k0 + kk) * lda + m0 + am);
                *reinterpret_cast<float4*>(&As[kk][am]) = v;
            }
        } else {
            int am  = t >> 1;
            int kq0 = (t & 1) * 2;
            #pragma unroll
            for (int r = 0; r < 2; r++) {
                int kq = kq0 + r;
                float4 v = *reinterpret_cast<const float4*>(A + (long)(m0 + am) * lda + k0 + kq * 4);
                As[kq * 4 + 0][am] = v.x;
                As[kq * 4 + 1][am] = v.y;
                As[kq * 4 + 2][am] = v.z;
                As[kq * 4 + 3][am] = v.w;
            }
        }
        // ---- load B tile into Bs[k][n]
        if (TRB == 0) {
            int bk = t >> 5;
            int bn = (t & 31) * 4;
            #pragma unroll
            for (int r = 0; r < 2; r++) {
                int kk = bk + r * 8;
                float4 v = *reinterpret_cast<const float4*>(B + (long)(k0 + kk) * ldb + n0 + bn);
                *reinterpret_cast<float4*>(&Bs[kk][bn]) = v;
            }
        } else {
            int bn  = t >> 1;
            int kq0 = (t & 1) * 2;
            #pragma unroll
            for (int r = 0; r < 2; r++) {
                int kq = kq0 + r;
                float4 v = *reinterpret_cast<const float4*>(B + (long)(n0 + bn) * ldb + k0 + kq * 4);
                Bs[kq * 4 + 0][bn] = v.x;
                Bs[kq * 4 + 1][bn] = v.y;
                Bs[kq * 4 + 2][bn] = v.z;
                Bs[kq * 4 + 3][bn] = v.w;
            }
        }
        __syncthreads();

        #pragma unroll
        for (int k = 0; k < BK; k++) {
            float4 a0 = *reinterpret_cast<const float4*>(&As[k][mb]);
            float4 a1 = *reinterpret_cast<const float4*>(&As[k][mb + 16]);
            ulonglong2 b0 = *reinterpret_cast<const ulonglong2*>(&Bs[k][nb]);
            ulonglong2 b1 = *reinterpret_cast<const ulonglong2*>(&Bs[k][nb + 32]);
            float a_[8] = {a0.x, a0.y, a0.z, a0.w, a1.x, a1.y, a1.z, a1.w};
            #pragma unroll
            for (int r = 0; r < 8; r++) {
                unsigned long long ap = pack2(a_[r]);
                ffma2(acc[r][0], ap, b0.x);
                ffma2(acc[r][1], ap, b0.y);
                ffma2(acc[r][2], ap, b1.x);
                ffma2(acc[r][3], ap, b1.y);
            }
        }
        __syncthreads();
    }

    // ---- epilogue
    #pragma unroll
    for (int r = 0; r < 8; r++) {
        int m = m0 + mb + ((r < 4) ? r : (r + 12));   // second half at +16
        float bv = BIAS ? bias[m] : 0.0f;
        #pragma unroll
        for (int j = 0; j < 4; j++) {
            int n = n0 + nb + ((j & 1) * 2) + ((j >> 1) * 32);
            float lo = __uint_as_float((unsigned int)(acc[r][j] & 0xffffffffull));
            float hi = __uint_as_float((unsigned int)(acc[r][j] >> 32));
            float2 out;
            out.x = fmaf(alpha, lo, bv);
            out.y = fmaf(alpha, hi, bv);
            if (RES) {
                const float* R = Rb + (long)blockIdx.z * sR;
                float2 rr = *reinterpret_cast<const float2*>(R + (long)m * ldc + n);
                out.x += rr.x;
                out.y += rr.y;
            }
            *reinterpret_cast<float2*>(C + (long)m * ldc + n) = out;
        }
    }
}

// ---------------- row softmax over last dim (4096) ----------------
__global__ void softmax_kernel(float* __restrict__ S) {
    float* p = S + (size_t)blockIdx.x * L_DIM;
    int t = threadIdx.x;
    float4 v[4];
    #pragma unroll
    for (int i = 0; i < 4; i++)
        v[i] = *reinterpret_cast<const float4*>(p + 4 * (i * 256 + t));

    float mx = -3.4e38f;
    #pragma unroll
    for (int i = 0; i < 4; i++)
        mx = fmaxf(mx, fmaxf(fmaxf(v[i].x, v[i].y), fmaxf(v[i].z, v[i].w)));
    #pragma unroll
    for (int o = 16; o; o >>= 1) mx = fmaxf(mx, __shfl_xor_sync(0xffffffffu, mx, o));

    __shared__ float red[8];
    if ((t & 31) == 0) red[t >> 5] = mx;
    __syncthreads();
    #pragma unroll
    for (int w = 0; w < 8; w++) mx = fmaxf(mx, red[w]);
    __syncthreads();

    float sum = 0.f;
    #pragma unroll
    for (int i = 0; i < 4; i++) {
        v[i].x = __expf(v[i].x - mx);
        v[i].y = __expf(v[i].y - mx);
        v[i].z = __expf(v[i].z - mx);
        v[i].w = __expf(v[i].w - mx);
        sum += v[i].x + v[i].y + v[i].z + v[i].w;
    }
    #pragma unroll
    for (int o = 16; o; o >>= 1) sum += __shfl_xor_sync(0xffffffffu, sum, o);
    if ((t & 31) == 0) red[t >> 5] = sum;
    __syncthreads();
    float tot = 0.f;
    #pragma unroll
    for (int w = 0; w < 8; w++) tot += red[w];
    float rinv = 1.0f / tot;

    #pragma unroll
    for (int i = 0; i < 4; i++) {
        v[i].x *= rinv; v[i].y *= rinv; v[i].z *= rinv; v[i].w *= rinv;
        *reinterpret_cast<float4*>(p + 4 * (i * 256 + t)) = v[i];
    }
}

// ---------------- launch ----------------
extern "C" void kernel_launch(void* const* d_in, const int* in_sizes, int n_in,
                              void* d_out, int out_size) {
    const float* x      = (const float*)d_in[0];
    const float* norm_g = (const float*)d_in[1];
    const float* norm_b = (const float*)d_in[2];
    const float* q_w    = (const float*)d_in[3];
    const float* q_b    = (const float*)d_in[4];
    const float* k_w    = (const float*)d_in[5];
    const float* k_b    = (const float*)d_in[6];
    const float* v_w    = (const float*)d_in[7];
    const float* v_b    = (const float*)d_in[8];
    const float* p_w    = (const float*)d_in[9];
    const float* p_b    = (const float*)d_in[10];
    float* out = (float*)d_out;

    float *h, *q, *k, *v, *h2, *s;
    cudaGetSymbolAddress((void**)&h,  g_h);
    cudaGetSymbolAddress((void**)&q,  g_q);
    cudaGetSymbolAddress((void**)&k,  g_k);
    cudaGetSymbolAddress((void**)&v,  g_v);
    cudaGetSymbolAddress((void**)&h2, g_h2);
    cudaGetSymbolAddress((void**)&s,  g_s);

    // 1) group norm
    gn_kernel<<<B_SZ * N_GROUPS, 256>>>(x, norm_g, norm_b);

    // 2) q, k, v = conv1x1(h)       Y[o,l] = sum_c W[o,c] * h[c,l] + b[o]
    dim3 gconv(L_DIM / BN, C_DIM / BM, B_SZ);      // (32, 2, 4)
    gemm_kernel<1, 0, true, false><<<gconv, 256>>>(q_w, h, q_b, nullptr, q,
        C_DIM, C_DIM, L_DIM, L_DIM, 1.0f, 0, CL, 0, CL);
    gemm_kernel<1, 0, true, false><<<gconv, 256>>>(k_w, h, k_b, nullptr, k,
        C_DIM, C_DIM, L_DIM, L_DIM, 1.0f, 0, CL, 0, CL);
    gemm_kernel<1, 0, true, false><<<gconv, 256>>>(v_w, h, v_b, nullptr, v,
        C_DIM, C_DIM, L_DIM, L_DIM, 1.0f, 0, CL, 0, CL);

    // 3) scores S[i,j] = (1/16) * sum_c q[c,i] * k[c,j]
    dim3 gsc(L_DIM / BN, L_DIM / BM, B_SZ);        // (32, 32, 4)
    gemm_kernel<0, 0, false, false><<<gsc, 256>>>(q, k, nullptr, nullptr, s,
        C_DIM, L_DIM, L_DIM, L_DIM, 0.0625f, CL, CL, 0, (long)LL);

    // 4) softmax rows
    softmax_kernel<<<B_SZ * L_DIM, 256>>>(s);

    // 5) h2[c,i] = sum_j v[c,j] * P[i,j]
    gemm_kernel<1, 1, false, false><<<gconv, 256>>>(v, s, nullptr, nullptr, h2,
        L_DIM, L_DIM, L_DIM, L_DIM, 1.0f, CL, (long)LL, 0, CL);

    // 6) out = x + proj(h2)
    gemm_kernel<1, 0, true, true><<<gconv, 256>>>(p_w, h2, p_b, x, out,
        C_DIM, C_DIM, L_DIM, L_DIM, 1.0f, 0, CL, CL, CL);
}

// round 9
// speedup vs baseline: 2.2621x; 2.2621x over previous
#include <cuda_runtime.h>

#define B_SZ 4
#define C_DIM 256
#define L_DIM 4096
#define N_GROUPS 32
#define C_PG 8

#define CL (C_DIM * L_DIM)
#define LL (L_DIM * L_DIM)

// ---------------- scratch ----------------
__device__ float g_h [B_SZ * CL];   // normalized input [C,L]
__device__ float g_q [B_SZ * CL];   // q_t [L,C]  (pre-scaled by 1/16, tf32-rounded)
__device__ float g_k [B_SZ * CL];   // k_t [L,C]  (tf32-rounded)
__device__ float g_v [B_SZ * CL];   // v   [C,L]  (tf32-rounded)
__device__ float g_h2[B_SZ * CL];   // h2_t [L,C]
__device__ float g_s [B_SZ * LL];   // scores / probs

// ---------------- helpers ----------------
__device__ __forceinline__ unsigned long long pack2(float v) {
    unsigned long long r;
    unsigned int u = __float_as_uint(v);
    asm("mov.b64 %0, {%1, %2};" : "=l"(r) : "r"(u), "r"(u));
    return r;
}
__device__ __forceinline__ void ffma2(unsigned long long& d,
                                      unsigned long long a,
                                      unsigned long long b) {
    asm("fma.rn.f32x2 %0, %1, %2, %0;" : "+l"(d) : "l"(a), "l"(b));
}
__device__ __forceinline__ float tf32r(float x) {
    unsigned int u;
    asm("cvt.rna.tf32.f32 %0, %1;" : "=r"(u) : "f"(x));
    return __uint_as_float(u);
}
__device__ __forceinline__ unsigned int smem_u32(const void* p) {
    unsigned int a;
    asm("{ .reg .u64 t; cvta.to.shared.u64 t, %1; cvt.u32.u64 %0, t; }"
        : "=r"(a) : "l"(p));
    return a;
}
__device__ __forceinline__ void cpa16(unsigned int dst, const void* src) {
    asm volatile("cp.async.cg.shared.global [%0], [%1], 16;"
                 :: "r"(dst), "l"(src) : "memory");
}

// ================= GroupNorm =================
__global__ void gn_kernel(const float* __restrict__ x,
                          const float* __restrict__ gamma,
                          const float* __restrict__ beta) {
    int b = blockIdx.x / N_GROUPS;
    int g = blockIdx.x % N_GROUPS;
    const int N = C_PG * L_DIM;
    size_t base = ((size_t)b * C_DIM + g * C_PG) * L_DIM;
    const float* xp = x + base;
    float* hp = g_h + base;
    int t = threadIdx.x;

    float s = 0.f, ss = 0.f;
    for (int i = t; i < N; i += 256) {
        float v = xp[i];
        s += v;
        ss = fmaf(v, v, ss);
    }
    #pragma unroll
    for (int o = 16; o; o >>= 1) {
        s  += __shfl_xor_sync(0xffffffffu, s,  o);
        ss += __shfl_xor_sync(0xffffffffu, ss, o);
    }
    __shared__ float shs[8], shss[8];
    if ((t & 31) == 0) { shs[t >> 5] = s; shss[t >> 5] = ss; }
    __syncthreads();
    float ts = 0.f, tss = 0.f;
    #pragma unroll
    for (int w = 0; w < 8; w++) { ts += shs[w]; tss += shss[w]; }

    float mean = ts / (float)N;
    float var  = tss / (float)N - mean * mean;
    float rstd = rsqrtf(var + 1e-6f);

    for (int i = t; i < N; i += 256) {
        int c = g * C_PG + (i >> 12);
        hp[i] = (xp[i] - mean) * rstd * gamma[c] + beta[c];
    }
}

// ================= FFMA2 SGEMM (convs / proj) =================
// C[m,n] = alpha * (sum_k Ahat[k,m]*Bhat[k,n] + bias) (+res) (+tf32 round)
// BMODE: 0 none, 1 bias[m], 2 bias[n]
#define BM 128
#define BN 128
#define BK 16
#define SROW 132

template<int TRA, int TRB, int BMODE, bool RES, bool RND>
__global__ __launch_bounds__(256, 2)
void gemm_kernel(const float* __restrict__ Ab, const float* __restrict__ Bb,
                 const float* __restrict__ bias, const float* __restrict__ Rb,
                 float* __restrict__ Cb,
                 int K, int lda, int ldb, int ldc, float alpha,
                 long sA, long sB, long sR, long sC) {
    const float* A = Ab + (long)blockIdx.z * sA;
    const float* B = Bb + (long)blockIdx.z * sB;
    float* C       = Cb + (long)blockIdx.z * sC;

    int m0 = blockIdx.y * BM;
    int n0 = blockIdx.x * BN;

    __shared__ __align__(16) float As[BK][SROW];
    __shared__ __align__(16) float Bs[BK][SROW];

    int t = threadIdx.x;
    int warp = t >> 5, lane = t & 31;
    int wm = warp >> 1, wn = warp & 1;
    int lm = lane >> 3, ln = lane & 7;
    int mb = wm * 32 + lm * 4;
    int nb = wn * 64 + ln * 4;

    unsigned long long acc[8][4];
    #pragma unroll
    for (int i = 0; i < 8; i++)
        #pragma unroll
        for (int j = 0; j < 4; j++) acc[i][j] = 0ull;

    for (int k0 = 0; k0 < K; k0 += BK) {
        if (TRA == 0) {
            int ak = t >> 5;
            int am = (t & 31) * 4;
            #pragma unroll
            for (int r = 0; r < 2; r++) {
                int kk = ak + r * 8;
                float4 v = *reinterpret_cast<const float4*>(A + (long)(k0 + kk) * lda + m0 + am);
                *reinterpret_cast<float4*>(&As[kk][am]) = v;
            }
        } else {
            int am  = t >> 1;
            int kq0 = (t & 1) * 2;
            #pragma unroll
            for (int r = 0; r < 2; r++) {
                int kq = kq0 + r;
                float4 v = *reinterpret_cast<const float4*>(A + (long)(m0 + am) * lda + k0 + kq * 4);
                As[kq * 4 + 0][am] = v.x;
                As[kq * 4 + 1][am] = v.y;
                As[kq * 4 + 2][am] = v.z;
                As[kq * 4 + 3][am] = v.w;
            }
        }
        if (TRB == 0) {
            int bk = t >> 5;
            int bn = (t & 31) * 4;
            #pragma unroll
            for (int r = 0; r < 2; r++) {
                int kk = bk + r * 8;
                float4 v = *reinterpret_cast<const float4*>(B + (long)(k0 + kk) * ldb + n0 + bn);
                *reinterpret_cast<float4*>(&Bs[kk][bn]) = v;
            }
        } else {
            int bn  = t >> 1;
            int kq0 = (t & 1) * 2;
            #pragma unroll
            for (int r = 0; r < 2; r++) {
                int kq = kq0 + r;
                float4 v = *reinterpret_cast<const float4*>(B + (long)(n0 + bn) * ldb + k0 + kq * 4);
                Bs[kq * 4 + 0][bn] = v.x;
                Bs[kq * 4 + 1][bn] = v.y;
                Bs[kq * 4 + 2][bn] = v.z;
                Bs[kq * 4 + 3][bn] = v.w;
            }
        }
        __syncthreads();

        #pragma unroll
        for (int k = 0; k < BK; k++) {
            float4 a0 = *reinterpret_cast<const float4*>(&As[k][mb]);
            float4 a1 = *reinterpret_cast<const float4*>(&As[k][mb + 16]);
            ulonglong2 b0 = *reinterpret_cast<const ulonglong2*>(&Bs[k][nb]);
            ulonglong2 b1 = *reinterpret_cast<const ulonglong2*>(&Bs[k][nb + 32]);
            float a_[8] = {a0.x, a0.y, a0.z, a0.w, a1.x, a1.y, a1.z, a1.w};
            #pragma unroll
            for (int r = 0; r < 8; r++) {
                unsigned long long ap = pack2(a_[r]);
                ffma2(acc[r][0], ap, b0.x);
                ffma2(acc[r][1], ap, b0.y);
                ffma2(acc[r][2], ap, b1.x);
                ffma2(acc[r][3], ap, b1.y);
            }
        }
        __syncthreads();
    }

    #pragma unroll
    for (int r = 0; r < 8; r++) {
        int m = m0 + mb + ((r < 4) ? r : (r + 12));
        float bm = (BMODE == 1) ? bias[m] : 0.0f;
        #pragma unroll
        for (int j = 0; j < 4; j++) {
            int n = n0 + nb + ((j & 1) * 2) + ((j >> 1) * 32);
            float lo = __uint_as_float((unsigned int)(acc[r][j] & 0xffffffffull));
            float hi = __uint_as_float((unsigned int)(acc[r][j] >> 32));
            float bnx = 0.f, bny = 0.f;
            if (BMODE == 2) {
                float2 t2 = *reinterpret_cast<const float2*>(bias + n);
                bnx = t2.x; bny = t2.y;
            }
            float2 out;
            out.x = alpha * (lo + bm + bnx);
            out.y = alpha * (hi + bm + bny);
            if (RES) {
                const float* R = Rb + (long)blockIdx.z * sR;
                float2 rr = *reinterpret_cast<const float2*>(R + (long)m * ldc + n);
                out.x += rr.x;
                out.y += rr.y;
            }
            if (RND) { out.x = tf32r(out.x); out.y = tf32r(out.y); }
            *reinterpret_cast<float2*>(C + (long)m * ldc + n) = out;
        }
    }
}

// ================= mma.sync tf32 GEMM =================
// D[m,n] = sum_k A[m*lda+k] * B[n*ldb+k]   (both operands K-major, tf32-rounded fp32)
// CTA tile 128x128, K_tile = 32, 8 warps (4m x 2n), warp tile 32x64.
#define RW 36                         // padded row length (floats) -> conflict-free frags
#define STG_F (2 * 128 * RW)          // floats per stage (A tile + B tile) = 9216

__global__ __launch_bounds__(256, 2)
void mma_gemm(const float* __restrict__ Ag, const float* __restrict__ Bg,
              float* __restrict__ Cg, int K, int lda, int ldb, int ldc,
              long sA, long sB, long sC) {
    extern __shared__ float dsm[];

    const int tid  = threadIdx.x;
    const int wid  = tid >> 5, lane = tid & 31;
    const int gid  = lane >> 2, tig = lane & 3;
    const int wm   = wid & 3,  wn  = wid >> 2;

    const float* A = Ag + (long)blockIdx.z * sA + (long)(blockIdx.y * 128) * lda;
    const float* B = Bg + (long)blockIdx.z * sB + (long)(blockIdx.x * 128) * ldb;

    const unsigned int sbase = smem_u32(dsm);

    float acc[16][4];
    #pragma unroll
    for (int i = 0; i < 16; i++) {
        acc[i][0] = 0.f; acc[i][1] = 0.f; acc[i][2] = 0.f; acc[i][3] = 0.f;
    }

    const int T = K >> 5;

    // ---- async load of one K_tile stage
    auto load_stage = [&](int stage, int t) {
        unsigned int sb = sbase + stage * STG_F * 4;
        const float* Ak = A + t * 32;
        const float* Bk = B + t * 32;
        #pragma unroll
        for (int i = 0; i < 4; i++) {
            int e = tid + i * 256;
            int m = e >> 3, kc = (e & 7) * 4;
            cpa16(sb + (m * RW + kc) * 4, Ak + (long)m * lda + kc);
        }
        #pragma unroll
        for (int i = 0; i < 4; i++) {
            int e = tid + i * 256;
            int n = e >> 3, kc = (e & 7) * 4;
            cpa16(sb + ((128 + n) * RW + kc) * 4, Bk + (long)n * ldb + kc);
        }
        asm volatile("cp.async.commit_group;" ::: "memory");
    };

    load_stage(0, 0);

    for (int t = 0; t < T; t++) {
        int st = t & 1;
        if (t + 1 < T) {
            load_stage(st ^ 1, t + 1);
            asm volatile("cp.async.wait_group 1;" ::: "memory");
        } else {
            asm volatile("cp.async.wait_group 0;" ::: "memory");
        }
        __syncthreads();

        const float* Abase = dsm + st * STG_F;
        const float* Bbase = Abase + 128 * RW;
        const float* ap0 = Abase + (wm * 32 + gid) * RW + tig;
        const float* bp0 = Bbase + (wn * 64 + gid) * RW + tig;

        #pragma unroll
        for (int kk = 0; kk < 32; kk += 8) {
            unsigned int a[2][4];
            #pragma unroll
            for (int ma = 0; ma < 2; ma++) {
                const float* p = ap0 + ma * 16 * RW + kk;
                a[ma][0] = __float_as_uint(p[0]);
                a[ma][1] = __float_as_uint(p[8 * RW]);
                a[ma][2] = __float_as_uint(p[4]);
                a[ma][3] = __float_as_uint(p[8 * RW + 4]);
            }
            #pragma unroll
            for (int na = 0; na < 8; na++) {
                const float* p = bp0 + na * 8 * RW + kk;
                unsigned int b0 = __float_as_uint(p[0]);
                unsigned int b1 = __float_as_uint(p[4]);
                #pragma unroll
                for (int ma = 0; ma < 2; ma++) {
                    float* d = acc[ma * 8 + na];
                    asm volatile(
                        "mma.sync.aligned.m16n8k8.row.col.f32.tf32.tf32.f32 "
                        "{%0,%1,%2,%3}, {%4,%5,%6,%7}, {%8,%9}, {%0,%1,%2,%3};"
                        : "+f"(d[0]), "+f"(d[1]), "+f"(d[2]), "+f"(d[3])
                        : "r"(a[ma][0]), "r"(a[ma][1]), "r"(a[ma][2]), "r"(a[ma][3]),
                          "r"(b0), "r"(b1));
                }
            }
        }
        __syncthreads();
    }

    // ---- epilogue
    float* Cb = Cg + (long)blockIdx.z * sC;
    long m0 = (long)blockIdx.y * 128 + wm * 32;
    int  n0 = blockIdx.x * 128 + wn * 64;
    #pragma unroll
    for (int ma = 0; ma < 2; ma++) {
        #pragma unroll
        for (int na = 0; na < 8; na++) {
            const float* d = acc[ma * 8 + na];
            long r0 = m0 + ma * 16 + gid;
            int  c  = n0 + na * 8 + tig * 2;
            *reinterpret_cast<float2*>(Cb + r0 * ldc + c)       = make_float2(d[0], d[1]);
            *reinterpret_cast<float2*>(Cb + (r0 + 8) * ldc + c) = make_float2(d[2], d[3]);
        }
    }
}

// ================= row softmax (+ tf32 round for PV input) =================
__global__ void softmax_kernel(float* __restrict__ S) {
    float* p = S + (size_t)blockIdx.x * L_DIM;
    int t = threadIdx.x;
    float4 v[4];
    #pragma unroll
    for (int i = 0; i < 4; i++)
        v[i] = *reinterpret_cast<const float4*>(p + 4 * (i * 256 + t));

    float mx = -3.4e38f;
    #pragma unroll
    for (int i = 0; i < 4; i++)
        mx = fmaxf(mx, fmaxf(fmaxf(v[i].x, v[i].y), fmaxf(v[i].z, v[i].w)));
    #pragma unroll
    for (int o = 16; o; o >>= 1) mx = fmaxf(mx, __shfl_xor_sync(0xffffffffu, mx, o));

    __shared__ float red[8];
    if ((t & 31) == 0) red[t >> 5] = mx;
    __syncthreads();
    #pragma unroll
    for (int w = 0; w < 8; w++) mx = fmaxf(mx, red[w]);
    __syncthreads();

    float sum = 0.f;
    #pragma unroll
    for (int i = 0; i < 4; i++) {
        v[i].x = __expf(v[i].x - mx);
        v[i].y = __expf(v[i].y - mx);
        v[i].z = __expf(v[i].z - mx);
        v[i].w = __expf(v[i].w - mx);
        sum += v[i].x + v[i].y + v[i].z + v[i].w;
    }
    #pragma unroll
    for (int o = 16; o; o >>= 1) sum += __shfl_xor_sync(0xffffffffu, sum, o);
    if ((t & 31) == 0) red[t >> 5] = sum;
    __syncthreads();
    float tot = 0.f;
    #pragma unroll
    for (int w = 0; w < 8; w++) tot += red[w];
    float rinv = 1.0f / tot;

    #pragma unroll
    for (int i = 0; i < 4; i++) {
        v[i].x = tf32r(v[i].x * rinv);
        v[i].y = tf32r(v[i].y * rinv);
        v[i].z = tf32r(v[i].z * rinv);
        v[i].w = tf32r(v[i].w * rinv);
        *reinterpret_cast<float4*>(p + 4 * (i * 256 + t)) = v[i];
    }
}

// ================= launch =================
extern "C" void kernel_launch(void* const* d_in, const int* in_sizes, int n_in,
                              void* d_out, int out_size) {
    const float* x      = (const float*)d_in[0];
    const float* norm_g = (const float*)d_in[1];
    const float* norm_b = (const float*)d_in[2];
    const float* q_w    = (const float*)d_in[3];
    const float* q_b    = (const float*)d_in[4];
    const float* k_w    = (const float*)d_in[5];
    const float* k_b    = (const float*)d_in[6];
    const float* v_w    = (const float*)d_in[7];
    const float* v_b    = (const float*)d_in[8];
    const float* p_w    = (const float*)d_in[9];
    const float* p_b    = (const float*)d_in[10];
    float* out = (float*)d_out;

    float *h, *qt, *kt, *v, *h2t, *s;
    cudaGetSymbolAddress((void**)&h,   g_h);
    cudaGetSymbolAddress((void**)&qt,  g_q);
    cudaGetSymbolAddress((void**)&kt,  g_k);
    cudaGetSymbolAddress((void**)&v,   g_v);
    cudaGetSymbolAddress((void**)&h2t, g_h2);
    cudaGetSymbolAddress((void**)&s,   g_s);

    const int DSM = 2 * STG_F * 4;   // 73728 B
    cudaFuncSetAttribute(mma_gemm, cudaFuncAttributeMaxDynamicSharedMemorySize, DSM);

    // 1) group norm
    gn_kernel<<<B_SZ * N_GROUPS, 256>>>(x, norm_g, norm_b);

    // 2) q_t[l,o] = (1/16)*(sum_c h[c,l]*qw[o,c] + qb[o])   [L,C], tf32-rounded
    dim3 gqt(C_DIM / BN, L_DIM / BM, B_SZ);   // (2, 32, 4)
    gemm_kernel<0, 1, 2, false, true><<<gqt, 256>>>(h, q_w, q_b, nullptr, qt,
        C_DIM, L_DIM, C_DIM, C_DIM, 0.0625f, CL, 0, 0, CL);
    gemm_kernel<0, 1, 2, false, true><<<gqt, 256>>>(h, k_w, k_b, nullptr, kt,
        C_DIM, L_DIM, C_DIM, C_DIM, 1.0f, CL, 0, 0, CL);

    //    v[o,l] = sum_c vw[o,c]*h[c,l] + vb[o]   [C,L], tf32-rounded
    dim3 gv(L_DIM / BN, C_DIM / BM, B_SZ);    // (32, 2, 4)
    gemm_kernel<1, 0, 1, false, true><<<gv, 256>>>(v_w, h, v_b, nullptr, v,
        C_DIM, C_DIM, L_DIM, L_DIM, 1.0f, 0, CL, 0, CL);

    // 3) S[i,j] = sum_c q_t[i,c]*k_t[j,c]   (1/16 folded into q_t)
    mma_gemm<<<dim3(L_DIM / 128, L_DIM / 128, B_SZ), 256, DSM>>>(
        qt, kt, s, C_DIM, C_DIM, C_DIM, L_DIM, CL, CL, (long)LL);

    // 4) softmax rows (+ tf32 round)
    softmax_kernel<<<B_SZ * L_DIM, 256>>>(s);

    // 5) h2_t[i,c] = sum_j P[i,j]*v[c,j]
    mma_gemm<<<dim3(C_DIM / 128, L_DIM / 128, B_SZ), 256, DSM>>>(
        s, v, h2t, L_DIM, L_DIM, L_DIM, C_DIM, (long)LL, CL, CL);

    // 6) out[o,i] = x[o,i] + sum_c pw[o,c]*h2_t[i,c] + pb[o]
    dim3 gpj(L_DIM / BN, C_DIM / BM, B_SZ);   // (32, 2, 4)
    gemm_kernel<1, 1, 1, true, false><<<gpj, 256>>>(p_w, h2t, p_b, x, out,
        C_DIM, C_DIM, C_DIM, L_DIM, 1.0f, 0, CL, CL, CL);
}

// round 10
// speedup vs baseline: 4.2701x; 1.8877x over previous
#include <cuda_runtime.h>
#include <cuda_fp16.h>

#define B_SZ 4
#define C_DIM 256
#define L_DIM 4096
#define N_GROUPS 32
#define C_PG 8

#define CL (C_DIM * L_DIM)
#define LL (L_DIM * L_DIM)

// ---------------- scratch ----------------
__device__ __half g_ht[B_SZ * CL];   // groupnorm output, TRANSPOSED [L,C], fp16
__device__ __half g_q [B_SZ * CL];   // q_t [L,C] fp16 (pre-scaled 1/16)
__device__ __half g_k [B_SZ * CL];   // k_t [L,C] fp16
__device__ __half g_v [B_SZ * CL];   // v   [C,L] fp16
__device__ float  g_h2[B_SZ * CL];   // h2_t [L,C] fp32
__device__ __half g_s [B_SZ * LL];   // scores / probs fp16 (128 MB)
__device__ __half g_w [3 * C_DIM * C_DIM];  // qw, kw, vw fp16

// ---------------- helpers ----------------
__device__ __forceinline__ unsigned long long pack2(float v) {
    unsigned long long r;
    unsigned int u = __float_as_uint(v);
    asm("mov.b64 %0, {%1, %2};" : "=l"(r) : "r"(u), "r"(u));
    return r;
}
__device__ __forceinline__ void ffma2(unsigned long long& d,
                                      unsigned long long a,
                                      unsigned long long b) {
    asm("fma.rn.f32x2 %0, %1, %2, %0;" : "+l"(d) : "l"(a), "l"(b));
}
__device__ __forceinline__ unsigned int smem_u32(const void* p) {
    unsigned int a;
    asm("{ .reg .u64 t; cvta.to.shared.u64 t, %1; cvt.u32.u64 %0, t; }"
        : "=r"(a) : "l"(p));
    return a;
}
__device__ __forceinline__ void cpa16(unsigned int dst, const void* src) {
    asm volatile("cp.async.cg.shared.global [%0], [%1], 16;"
                 :: "r"(dst), "l"(src) : "memory");
}

// ================= GroupNorm -> transposed fp16 output =================
__global__ void gn_kernel(const float* __restrict__ x,
                          const float* __restrict__ gamma,
                          const float* __restrict__ beta) {
    int b = blockIdx.x / N_GROUPS;
    int g = blockIdx.x % N_GROUPS;
    const int N = C_PG * L_DIM;
    int gc = g * C_PG;
    const float* xp = x + ((size_t)b * C_DIM + gc) * L_DIM;
    int t = threadIdx.x;

    float s = 0.f, ss = 0.f;
    for (int i = t; i < N; i += 256) {
        float v = xp[i];
        s += v;
        ss = fmaf(v, v, ss);
    }
    #pragma unroll
    for (int o = 16; o; o >>= 1) {
        s  += __shfl_xor_sync(0xffffffffu, s,  o);
        ss += __shfl_xor_sync(0xffffffffu, ss, o);
    }
    __shared__ float shs[8], shss[8];
    if ((t & 31) == 0) { shs[t >> 5] = s; shss[t >> 5] = ss; }
    __syncthreads();
    float ts = 0.f, tss = 0.f;
    #pragma unroll
    for (int w = 0; w < 8; w++) { ts += shs[w]; tss += shss[w]; }

    float mean = ts / (float)N;
    float var  = tss / (float)N - mean * mean;
    float rstd = rsqrtf(var + 1e-6f);

    // transposed write: thread -> (c = t&7, l strided); 8 lanes of same l
    // write 8 consecutive halves (16B) of h_t[l][gc..gc+7].
    int c = t & 7;
    float ga = gamma[gc + c], be = beta[gc + c];
    __half* hb = g_ht + (size_t)b * CL + gc + c;
    const float* xc = xp + (size_t)c * L_DIM;
    for (int l = (t >> 3); l < L_DIM; l += 32) {
        float val = (xc[l] - mean) * rstd * ga + be;
        hb[(size_t)l * C_DIM] = __float2half(val);
    }
}

// ================= weight fp32 -> fp16 =================
__global__ void wconv_kernel(const float* __restrict__ qw,
                             const float* __restrict__ kw,
                             const float* __restrict__ vw) {
    int i = blockIdx.x * 256 + threadIdx.x;
    g_w[i]                     = __float2half(qw[i]);
    g_w[C_DIM * C_DIM + i]     = __float2half(kw[i]);
    g_w[2 * C_DIM * C_DIM + i] = __float2half(vw[i]);
}

// ================= fp16 mma.sync GEMM =================
// D[m,n] = alpha*(sum_k A[m*lda+k]*B[n*ldb+k] + bias)  (both operands K-major fp16)
// CTA 128x128, K_tile=64, 8 warps (4m x 2n), warp tile 32x64, m16n8k16.
// BMODE: 0 none, 1 bias[m], 2 bias[n].  OUTF: write fp32 (else fp16).
#define RWH 72                     // padded row length in halves (64 + 8)
#define STG_H (256 * RWH)          // halves per stage (A 128 rows + B 128 rows)

template<int BMODE, bool OUTF>
__global__ __launch_bounds__(256, 2)
void hmma_gemm(const __half* __restrict__ Ag, const __half* __restrict__ Bg,
               const float* __restrict__ bias, void* __restrict__ Cg,
               int K, int lda, int ldb, int ldc, float alpha,
               long sA, long sB, long sC) {
    extern __shared__ __half dsmh[];

    const int tid = threadIdx.x;
    const int wid = tid >> 5, lane = tid & 31;
    const int gid = lane >> 2, tig = lane & 3;
    const int wm  = wid & 3,  wn  = wid >> 2;

    const __half* A = Ag + (long)blockIdx.z * sA + (long)(blockIdx.y * 128) * lda;
    const __half* B = Bg + (long)blockIdx.z * sB + (long)(blockIdx.x * 128) * ldb;

    const unsigned int sbase = smem_u32(dsmh);

    float acc[16][4];
    #pragma unroll
    for (int i = 0; i < 16; i++) {
        acc[i][0] = 0.f; acc[i][1] = 0.f; acc[i][2] = 0.f; acc[i][3] = 0.f;
    }

    const int T = K >> 6;     // K_tile = 64

    auto load_stage = [&](int stage, int t) {
        unsigned int sb = sbase + stage * STG_H * 2;
        const __half* Ak = A + t * 64;
        const __half* Bk = B + t * 64;
        #pragma unroll
        for (int i = 0; i < 4; i++) {
            int e = tid + i * 256;
            int r = e >> 3, k8 = e & 7;
            cpa16(sb + (r * RWH + k8 * 8) * 2, Ak + (long)r * lda + k8 * 8);
        }
        #pragma unroll
        for (int i = 0; i < 4; i++) {
            int e = tid + i * 256;
            int r = e >> 3, k8 = e & 7;
            cpa16(sb + ((128 + r) * RWH + k8 * 8) * 2, Bk + (long)r * ldb + k8 * 8);
        }
        asm volatile("cp.async.commit_group;" ::: "memory");
    };

    load_stage(0, 0);

    for (int t = 0; t < T; t++) {
        int st = t & 1;
        if (t + 1 < T) {
            load_stage(st ^ 1, t + 1);
            asm volatile("cp.async.wait_group 1;" ::: "memory");
        } else {
            asm volatile("cp.async.wait_group 0;" ::: "memory");
        }
        __syncthreads();

        const __half* Abase = dsmh + st * STG_H;
        const __half* ap0 = Abase + (wm * 32 + gid) * RWH + 2 * tig;
        const __half* bp0 = Abase + (128 + wn * 64 + gid) * RWH + 2 * tig;

        #pragma unroll
        for (int kk = 0; kk < 64; kk += 16) {
            unsigned int a[2][4];
            #pragma unroll
            for (int ma = 0; ma < 2; ma++) {
                const __half* p = ap0 + ma * 16 * RWH + kk;
                a[ma][0] = *reinterpret_cast<const unsigned int*>(p);
                a[ma][1] = *reinterpret_cast<const unsigned int*>(p + 8 * RWH);
                a[ma][2] = *reinterpret_cast<const unsigned int*>(p + 8);
                a[ma][3] = *reinterpret_cast<const unsigned int*>(p + 8 * RWH + 8);
            }
            #pragma unroll
            for (int na = 0; na < 8; na++) {
                const __half* p = bp0 + na * 8 * RWH + kk;
                unsigned int b0 = *reinterpret_cast<const unsigned int*>(p);
                unsigned int b1 = *reinterpret_cast<const unsigned int*>(p + 8);
                #pragma unroll
                for (int ma = 0; ma < 2; ma++) {
                    float* d = acc[ma * 8 + na];
                    asm volatile(
                        "mma.sync.aligned.m16n8k16.row.col.f32.f16.f16.f32 "
                        "{%0,%1,%2,%3}, {%4,%5,%6,%7}, {%8,%9}, {%0,%1,%2,%3};"
                        : "+f"(d[0]), "+f"(d[1]), "+f"(d[2]), "+f"(d[3])
                        : "r"(a[ma][0]), "r"(a[ma][1]), "r"(a[ma][2]), "r"(a[ma][3]),
                          "r"(b0), "r"(b1));
                }
            }
        }
        __syncthreads();
    }

    // ---- epilogue
    long m0 = (long)blockIdx.y * 128 + wm * 32;
    int  n0 = blockIdx.x * 128 + wn * 64;
    #pragma unroll
    for (int ma = 0; ma < 2; ma++) {
        #pragma unroll
        for (int na = 0; na < 8; na++) {
            const float* d = acc[ma * 8 + na];
            long r0 = m0 + ma * 16 + gid;
            int  c  = n0 + na * 8 + tig * 2;
            float b00 = 0.f, b01 = 0.f, b10 = 0.f, b11 = 0.f;
            if (BMODE == 1) {
                b00 = b01 = bias[r0];
                b10 = b11 = bias[r0 + 8];
            } else if (BMODE == 2) {
                float2 bb = *reinterpret_cast<const float2*>(bias + c);
                b00 = b10 = bb.x;
                b01 = b11 = bb.y;
            }
            float v0 = alpha * (d[0] + b00);
            float v1 = alpha * (d[1] + b01);
            float v2 = alpha * (d[2] + b10);
            float v3 = alpha * (d[3] + b11);
            if (OUTF) {
                float* Cf = (float*)Cg + (long)blockIdx.z * sC;
                *reinterpret_cast<float2*>(Cf + r0 * ldc + c)       = make_float2(v0, v1);
                *reinterpret_cast<float2*>(Cf + (r0 + 8) * ldc + c) = make_float2(v2, v3);
            } else {
                __half* Ch = (__half*)Cg + (long)blockIdx.z * sC;
                *reinterpret_cast<__half2*>(Ch + r0 * ldc + c)       = __floats2half2_rn(v0, v1);
                *reinterpret_cast<__half2*>(Ch + (r0 + 8) * ldc + c) = __floats2half2_rn(v2, v3);
            }
        }
    }
}

// ================= FFMA2 SGEMM (proj only) =================
#define BM 128
#define BN 128
#define BK 16
#define SROW 132

template<int TRA, int TRB, int BMODE, bool RES>
__global__ __launch_bounds__(256, 2)
void gemm_kernel(const float* __restrict__ Ab, const float* __restrict__ Bb,
                 const float* __restrict__ bias, const float* __restrict__ Rb,
                 float* __restrict__ Cb,
                 int K, int lda, int ldb, int ldc, float alpha,
                 long sA, long sB, long sR, long sC) {
    const float* A = Ab + (long)blockIdx.z * sA;
    const float* B = Bb + (long)blockIdx.z * sB;
    float* C       = Cb + (long)blockIdx.z * sC;

    int m0 = blockIdx.y * BM;
    int n0 = blockIdx.x * BN;

    __shared__ __align__(16) float As[BK][SROW];
    __shared__ __align__(16) float Bs[BK][SROW];

    int t = threadIdx.x;
    int warp = t >> 5, lane = t & 31;
    int wm = warp >> 1, wn = warp & 1;
    int lm = lane >> 3, ln = lane & 7;
    int mb = wm * 32 + lm * 4;
    int nb = wn * 64 + ln * 4;

    unsigned long long acc[8][4];
    #pragma unroll
    for (int i = 0; i < 8; i++)
        #pragma unroll
        for (int j = 0; j < 4; j++) acc[i][j] = 0ull;

    for (int k0 = 0; k0 < K; k0 += BK) {
        if (TRA == 0) {
            int ak = t >> 5;
            int am = (t & 31) * 4;
            #pragma unroll
            for (int r = 0; r < 2; r++) {
                int kk = ak + r * 8;
                float4 v = *reinterpret_cast<const float4*>(A + (long)(k0 + kk) * lda + m0 + am);
                *reinterpret_cast<float4*>(&As[kk][am]) = v;
            }
        } else {
            int am  = t >> 1;
            int kq0 = (t & 1) * 2;
            #pragma unroll
            for (int r = 0; r < 2; r++) {
                int kq = kq0 + r;
                float4 v = *reinterpret_cast<const float4*>(A + (long)(m0 + am) * lda + k0 + kq * 4);
                As[kq * 4 + 0][am] = v.x;
                As[kq * 4 + 1][am] = v.y;
                As[kq * 4 + 2][am] = v.z;
                As[kq * 4 + 3][am] = v.w;
            }
        }
        if (TRB == 0) {
            int bk = t >> 5;
            int bn = (t & 31) * 4;
            #pragma unroll
            for (int r = 0; r < 2; r++) {
                int kk = bk + r * 8;
                float4 v = *reinterpret_cast<const float4*>(B + (long)(k0 + kk) * ldb + n0 + bn);
                *reinterpret_cast<float4*>(&Bs[kk][bn]) = v;
            }
        } else {
            int bn  = t >> 1;
            int kq0 = (t & 1) * 2;
            #pragma unroll
            for (int r = 0; r < 2; r++) {
                int kq = kq0 + r;
                float4 v = *reinterpret_cast<const float4*>(B + (long)(n0 + bn) * ldb + k0 + kq * 4);
                Bs[kq * 4 + 0][bn] = v.x;
                Bs[kq * 4 + 1][bn] = v.y;
                Bs[kq * 4 + 2][bn] = v.z;
                Bs[kq * 4 + 3][bn] = v.w;
            }
        }
        __syncthreads();

        #pragma unroll
        for (int k = 0; k < BK; k++) {
            float4 a0 = *reinterpret_cast<const float4*>(&As[k][mb]);
            float4 a1 = *reinterpret_cast<const float4*>(&As[k][mb + 16]);
            ulonglong2 b0 = *reinterpret_cast<const ulonglong2*>(&Bs[k][nb]);
            ulonglong2 b1 = *reinterpret_cast<const ulonglong2*>(&Bs[k][nb + 32]);
            float a_[8] = {a0.x, a0.y, a0.z, a0.w, a1.x, a1.y, a1.z, a1.w};
            #pragma unroll
            for (int r = 0; r < 8; r++) {
                unsigned long long ap = pack2(a_[r]);
                ffma2(acc[r][0], ap, b0.x);
                ffma2(acc[r][1], ap, b0.y);
                ffma2(acc[r][2], ap, b1.x);
                ffma2(acc[r][3], ap, b1.y);
            }
        }
        __syncthreads();
    }

    #pragma unroll
    for (int r = 0; r < 8; r++) {
        int m = m0 + mb + ((r < 4) ? r : (r + 12));
        float bm = (BMODE == 1) ? bias[m] : 0.0f;
        #pragma unroll
        for (int j = 0; j < 4; j++) {
            int n = n0 + nb + ((j & 1) * 2) + ((j >> 1) * 32);
            float lo = __uint_as_float((unsigned int)(acc[r][j] & 0xffffffffull));
            float hi = __uint_as_float((unsigned int)(acc[r][j] >> 32));
            float2 out;
            out.x = alpha * (lo + bm);
            out.y = alpha * (hi + bm);
            if (RES) {
                const float* R = Rb + (long)blockIdx.z * sR;
                float2 rr = *reinterpret_cast<const float2*>(R + (long)m * ldc + n);
                out.x += rr.x;
                out.y += rr.y;
            }
            *reinterpret_cast<float2*>(C + (long)m * ldc + n) = out;
        }
    }
}

// ================= row softmax on fp16 S =================
__global__ void softmax_kernel(__half* __restrict__ S) {
    __half* p = S + (size_t)blockIdx.x * L_DIM;
    int t = threadIdx.x;

    uint4 u[2];
    u[0] = reinterpret_cast<const uint4*>(p)[t];
    u[1] = reinterpret_cast<const uint4*>(p)[t + 256];

    float f[16];
    #pragma unroll
    for (int i = 0; i < 2; i++) {
        const unsigned int* w = reinterpret_cast<const unsigned int*>(&u[i]);
        #pragma unroll
        for (int j = 0; j < 4; j++) {
            float2 ff = __half22float2(*reinterpret_cast<const __half2*>(&w[j]));
            f[i * 8 + j * 2]     = ff.x;
            f[i * 8 + j * 2 + 1] = ff.y;
        }
    }

    float mx = -3.4e38f;
    #pragma unroll
    for (int i = 0; i < 16; i++) mx = fmaxf(mx, f[i]);
    #pragma unroll
    for (int o = 16; o; o >>= 1) mx = fmaxf(mx, __shfl_xor_sync(0xffffffffu, mx, o));

    __shared__ float red[8];
    if ((t & 31) == 0) red[t >> 5] = mx;
    __syncthreads();
    #pragma unroll
    for (int w = 0; w < 8; w++) mx = fmaxf(mx, red[w]);
    __syncthreads();

    float sum = 0.f;
    #pragma unroll
    for (int i = 0; i < 16; i++) {
        f[i] = __expf(f[i] - mx);
        sum += f[i];
    }
    #pragma unroll
    for (int o = 16; o; o >>= 1) sum += __shfl_xor_sync(0xffffffffu, sum, o);
    if ((t & 31) == 0) red[t >> 5] = sum;
    __syncthreads();
    float tot = 0.f;
    #pragma unroll
    for (int w = 0; w < 8; w++) tot += red[w];
    float rinv = 1.0f / tot;

    #pragma unroll
    for (int i = 0; i < 2; i++) {
        unsigned int* w = reinterpret_cast<unsigned int*>(&u[i]);
        #pragma unroll
        for (int j = 0; j < 4; j++) {
            __half2 h2 = __floats2half2_rn(f[i * 8 + j * 2] * rinv,
                                           f[i * 8 + j * 2 + 1] * rinv);
            w[j] = *reinterpret_cast<unsigned int*>(&h2);
        }
    }
    reinterpret_cast<uint4*>(p)[t]       = u[0];
    reinterpret_cast<uint4*>(p)[t + 256] = u[1];
}

// ================= launch =================
extern "C" void kernel_launch(void* const* d_in, const int* in_sizes, int n_in,
                              void* d_out, int out_size) {
    const float* x      = (const float*)d_in[0];
    const float* norm_g = (const float*)d_in[1];
    const float* norm_b = (const float*)d_in[2];
    const float* q_w    = (const float*)d_in[3];
    const float* q_b    = (const float*)d_in[4];
    const float* k_w    = (const float*)d_in[5];
    const float* k_b    = (const float*)d_in[6];
    const float* v_w    = (const float*)d_in[7];
    const float* v_b    = (const float*)d_in[8];
    const float* p_w    = (const float*)d_in[9];
    const float* p_b    = (const float*)d_in[10];
    float* out = (float*)d_out;

    __half *ht, *qt, *kt, *v, *s, *w;
    float *h2t;
    cudaGetSymbolAddress((void**)&ht,  g_ht);
    cudaGetSymbolAddress((void**)&qt,  g_q);
    cudaGetSymbolAddress((void**)&kt,  g_k);
    cudaGetSymbolAddress((void**)&v,   g_v);
    cudaGetSymbolAddress((void**)&h2t, g_h2);
    cudaGetSymbolAddress((void**)&s,   g_s);
    cudaGetSymbolAddress((void**)&w,   g_w);

    const int DSM = 2 * STG_H * 2;   // 73728 B
    cudaFuncSetAttribute(hmma_gemm<2, false>, cudaFuncAttributeMaxDynamicSharedMemorySize, DSM);
    cudaFuncSetAttribute(hmma_gemm<1, false>, cudaFuncAttributeMaxDynamicSharedMemorySize, DSM);
    cudaFuncSetAttribute(hmma_gemm<0, false>, cudaFuncAttributeMaxDynamicSharedMemorySize, DSM);
    cudaFuncSetAttribute(hmma_gemm<0, true>,  cudaFuncAttributeMaxDynamicSharedMemorySize, DSM);

    // 0) weights -> fp16
    wconv_kernel<<<C_DIM * C_DIM / 256, 256>>>(q_w, k_w, v_w);

    // 1) group norm -> h_t [L,C] fp16
    gn_kernel<<<B_SZ * N_GROUPS, 256>>>(x, norm_g, norm_b);

    const __half* wq = w;
    const __half* wk = w + C_DIM * C_DIM;
    const __half* wv = w + 2 * C_DIM * C_DIM;

    // 2) convs (all fp16 HMMA):
    //    q_t[l,o] = (1/16)*(sum_c h_t[l,c]*qw[o,c] + qb[o])
    hmma_gemm<2, false><<<dim3(2, 32, B_SZ), 256, DSM>>>(
        ht, wq, q_b, qt, C_DIM, C_DIM, C_DIM, C_DIM, 0.0625f, CL, 0, CL);
    //    k_t[l,o]
    hmma_gemm<2, false><<<dim3(2, 32, B_SZ), 256, DSM>>>(
        ht, wk, k_b, kt, C_DIM, C_DIM, C_DIM, C_DIM, 1.0f, CL, 0, CL);
    //    v[o,l] = sum_c vw[o,c]*h_t[l,c] + vb[o]
    hmma_gemm<1, false><<<dim3(32, 2, B_SZ), 256, DSM>>>(
        wv, ht, v_b, v, C_DIM, C_DIM, C_DIM, L_DIM, 1.0f, 0, CL, CL);

    // 3) S[i,j] = sum_c q_t[i,c]*k_t[j,c]   (1/16 folded into q_t)
    hmma_gemm<0, false><<<dim3(32, 32, B_SZ), 256, DSM>>>(
        qt, kt, nullptr, s, C_DIM, C_DIM, C_DIM, L_DIM, 1.0f, CL, CL, (long)LL);

    // 4) softmax rows (fp16 in/out)
    softmax_kernel<<<B_SZ * L_DIM, 256>>>(s);

    // 5) h2_t[i,c] = sum_j P[i,j]*v[c,j]  -> fp32
    hmma_gemm<0, true><<<dim3(2, 32, B_SZ), 256, DSM>>>(
        s, v, nullptr, h2t, L_DIM, L_DIM, L_DIM, C_DIM, 1.0f, (long)LL, CL, CL);

    // 6) out[o,i] = x[o,i] + sum_c pw[o,c]*h2_t[i,c] + pb[o]   (fp32 FFMA2)
    gemm_kernel<1, 1, 1, true><<<dim3(32, 2, B_SZ), 256>>>(
        p_w, h2t, p_b, x, out,
        C_DIM, C_DIM, C_DIM, L_DIM, 1.0f, 0, CL, CL, CL);
}

// round 11
// speedup vs baseline: 4.6756x; 1.0950x over previous
#include <cuda_runtime.h>
#include <cuda_fp16.h>

#define B_SZ 4
#define C_DIM 256
#define L_DIM 4096
#define N_GROUPS 32
#define C_PG 8

#define CL (C_DIM * L_DIM)
#define LL (L_DIM * L_DIM)

// ---------------- scratch ----------------
__device__ __half g_ht [B_SZ * CL];        // groupnorm out, [L,C] fp16
__device__ __half g_qk [B_SZ * L_DIM * 512]; // q_t|k_t [L, 512] fp16 (q pre-scaled 1/16)
__device__ __half g_v  [B_SZ * CL];        // v [C,L] fp16
__device__ __half g_h2 [B_SZ * CL];        // h2_t [L,C] fp16
__device__ __half g_s  [B_SZ * LL];        // scores / probs fp16
__device__ __half g_wqk[512 * C_DIM];      // stacked [wq/16 ; wk] fp16
__device__ __half g_wv [C_DIM * C_DIM];
__device__ __half g_wp [C_DIM * C_DIM];
__device__ float  g_bqk[512];              // stacked [qb/16 ; kb]

// ---------------- helpers ----------------
__device__ __forceinline__ unsigned int smem_u32(const void* p) {
    unsigned int a;
    asm("{ .reg .u64 t; cvta.to.shared.u64 t, %1; cvt.u32.u64 %0, t; }"
        : "=r"(a) : "l"(p));
    return a;
}
__device__ __forceinline__ void cpa16(unsigned int dst, const void* src) {
    asm volatile("cp.async.cg.shared.global [%0], [%1], 16;"
                 :: "r"(dst), "l"(src) : "memory");
}
__device__ __forceinline__ void ldsm4(unsigned int* r, unsigned int addr) {
    asm volatile("ldmatrix.sync.aligned.m8n8.x4.shared.b16 {%0,%1,%2,%3}, [%4];"
                 : "=r"(r[0]), "=r"(r[1]), "=r"(r[2]), "=r"(r[3]) : "r"(addr));
}

// ================= GroupNorm -> transposed fp16 =================
__global__ void gn_kernel(const float* __restrict__ x,
                          const float* __restrict__ gamma,
                          const float* __restrict__ beta) {
    int b = blockIdx.x / N_GROUPS;
    int g = blockIdx.x % N_GROUPS;
    const int N = C_PG * L_DIM;
    int gc = g * C_PG;
    const float* xp = x + ((size_t)b * C_DIM + gc) * L_DIM;
    int t = threadIdx.x;

    float s = 0.f, ss = 0.f;
    for (int i = t; i < N; i += 256) {
        float v = xp[i];
        s += v;
        ss = fmaf(v, v, ss);
    }
    #pragma unroll
    for (int o = 16; o; o >>= 1) {
        s  += __shfl_xor_sync(0xffffffffu, s,  o);
        ss += __shfl_xor_sync(0xffffffffu, ss, o);
    }
    __shared__ float shs[8], shss[8];
    if ((t & 31) == 0) { shs[t >> 5] = s; shss[t >> 5] = ss; }
    __syncthreads();
    float ts = 0.f, tss = 0.f;
    #pragma unroll
    for (int w = 0; w < 8; w++) { ts += shs[w]; tss += shss[w]; }

    float mean = ts / (float)N;
    float var  = tss / (float)N - mean * mean;
    float rstd = rsqrtf(var + 1e-6f);

    int c = t & 7;
    float ga = gamma[gc + c], be = beta[gc + c];
    __half* hb = g_ht + (size_t)b * CL + gc + c;
    const float* xc = xp + (size_t)c * L_DIM;
    for (int l = (t >> 3); l < L_DIM; l += 32) {
        float val = (xc[l] - mean) * rstd * ga + be;
        hb[(size_t)l * C_DIM] = __float2half(val);
    }
}

// ================= weight/bias fp32 -> fp16 =================
__global__ void wconv_kernel(const float* __restrict__ qw, const float* __restrict__ kw,
                             const float* __restrict__ vw, const float* __restrict__ pw,
                             const float* __restrict__ qb, const float* __restrict__ kb) {
    int i = blockIdx.x * 256 + threadIdx.x;
    g_wqk[i]                 = __float2half(qw[i] * 0.0625f);
    g_wqk[C_DIM * C_DIM + i] = __float2half(kw[i]);
    g_wv[i]                  = __float2half(vw[i]);
    g_wp[i]                  = __float2half(pw[i]);
    if (i < 256) {
        g_bqk[i]       = qb[i] * 0.0625f;
        g_bqk[256 + i] = kb[i];
    }
}

// ================= fp16 mma.sync GEMM (ldmatrix fragments) =================
// D[m,n] = alpha*(sum_k A[m*lda+k]*B[n*ldb+k] + bias)  (+ fp32 residual)
// CTA 128x128, K_tile=64, 8 warps (4m x 2n), warp tile 32x64, m16n8k16.
// BMODE: 0 none, 1 bias[m], 2 bias[n].  OUTF: fp32 out.  RES: add fp32 residual.
#define RWH 72
#define STG_H (256 * RWH)

template<int BMODE, bool OUTF, bool RES>
__global__ __launch_bounds__(256, 2)
void hmma_gemm(const __half* __restrict__ Ag, const __half* __restrict__ Bg,
               const float* __restrict__ bias, const float* __restrict__ Rg,
               void* __restrict__ Cg,
               int K, int lda, int ldb, int ldc, float alpha,
               long sA, long sB, long sR, long sC) {
    extern __shared__ __half dsmh[];

    const int tid = threadIdx.x;
    const int wid = tid >> 5, lane = tid & 31;
    const int gid = lane >> 2, tig = lane & 3;
    const int wm  = wid & 3,  wn  = wid >> 2;

    const __half* A = Ag + (long)blockIdx.z * sA + (long)(blockIdx.y * 128) * lda;
    const __half* B = Bg + (long)blockIdx.z * sB + (long)(blockIdx.x * 128) * ldb;

    const unsigned int sbase = smem_u32(dsmh);

    float acc[16][4];
    #pragma unroll
    for (int i = 0; i < 16; i++) {
        acc[i][0] = 0.f; acc[i][1] = 0.f; acc[i][2] = 0.f; acc[i][3] = 0.f;
    }

    const int T = K >> 6;

    auto load_stage = [&](int stage, int t) {
        unsigned int sb = sbase + stage * STG_H * 2;
        const __half* Ak = A + t * 64;
        const __half* Bk = B + t * 64;
        #pragma unroll
        for (int i = 0; i < 4; i++) {
            int e = tid + i * 256;
            int r = e >> 3, k8 = e & 7;
            cpa16(sb + (r * RWH + k8 * 8) * 2, Ak + (long)r * lda + k8 * 8);
        }
        #pragma unroll
        for (int i = 0; i < 4; i++) {
            int e = tid + i * 256;
            int r = e >> 3, k8 = e & 7;
            cpa16(sb + ((128 + r) * RWH + k8 * 8) * 2, Bk + (long)r * ldb + k8 * 8);
        }
        asm volatile("cp.async.commit_group;" ::: "memory");
    };

    load_stage(0, 0);

    // per-lane ldmatrix row/col offsets (halves): row = lane&15, k-half = (lane>>4)*8
    const unsigned int a_off = ((wm * 32 + (lane & 15)) * RWH + (lane >> 4) * 8) * 2;
    const unsigned int b_off = ((128 + wn * 64 + (lane & 15)) * RWH + (lane >> 4) * 8) * 2;

    for (int t = 0; t < T; t++) {
        int st = t & 1;
        if (t + 1 < T) {
            load_stage(st ^ 1, t + 1);
            asm volatile("cp.async.wait_group 1;" ::: "memory");
        } else {
            asm volatile("cp.async.wait_group 0;" ::: "memory");
        }
        __syncthreads();

        unsigned int sb = sbase + st * STG_H * 2;
        unsigned int aa = sb + a_off;
        unsigned int bb = sb + b_off;

        #pragma unroll
        for (int kk = 0; kk < 4; kk++) {      // kk*16 within K_tile=64
            unsigned int koff = kk * 16 * 2;
            unsigned int a[2][4];
            ldsm4(a[0], aa + koff);
            ldsm4(a[1], aa + 16 * RWH * 2 + koff);
            unsigned int bfr[4][4];           // bfr[j] covers n = j*16..j*16+15
            #pragma unroll
            for (int j = 0; j < 4; j++)
                ldsm4(bfr[j], bb + j * 16 * RWH * 2 + koff);

            #pragma unroll
            for (int na = 0; na < 8; na++) {
                int j = na >> 1, h = na & 1;
                unsigned int b0 = bfr[j][h];       // k0-7
                unsigned int b1 = bfr[j][h + 2];   // k8-15
                #pragma unroll
                for (int ma = 0; ma < 2; ma++) {
                    float* d = acc[ma * 8 + na];
                    asm volatile(
                        "mma.sync.aligned.m16n8k16.row.col.f32.f16.f16.f32 "
                        "{%0,%1,%2,%3}, {%4,%5,%6,%7}, {%8,%9}, {%0,%1,%2,%3};"
                        : "+f"(d[0]), "+f"(d[1]), "+f"(d[2]), "+f"(d[3])
                        : "r"(a[ma][0]), "r"(a[ma][1]), "r"(a[ma][2]), "r"(a[ma][3]),
                          "r"(b0), "r"(b1));
                }
            }
        }
        __syncthreads();
    }

    // ---- epilogue
    long m0 = (long)blockIdx.y * 128 + wm * 32;
    int  n0 = blockIdx.x * 128 + wn * 64;
    #pragma unroll
    for (int ma = 0; ma < 2; ma++) {
        #pragma unroll
        for (int na = 0; na < 8; na++) {
            const float* d = acc[ma * 8 + na];
            long r0 = m0 + ma * 16 + gid;
            int  c  = n0 + na * 8 + tig * 2;
            float b00 = 0.f, b01 = 0.f, b10 = 0.f, b11 = 0.f;
            if (BMODE == 1) {
                b00 = b01 = bias[r0];
                b10 = b11 = bias[r0 + 8];
            } else if (BMODE == 2) {
                float2 bb2 = *reinterpret_cast<const float2*>(bias + c);
                b00 = b10 = bb2.x;
                b01 = b11 = bb2.y;
            }
            float v0 = alpha * (d[0] + b00);
            float v1 = alpha * (d[1] + b01);
            float v2 = alpha * (d[2] + b10);
            float v3 = alpha * (d[3] + b11);
            if (RES) {
                const float* R = Rg + (long)blockIdx.z * sR;
                float2 r1 = *reinterpret_cast<const float2*>(R + r0 * ldc + c);
                float2 r2 = *reinterpret_cast<const float2*>(R + (r0 + 8) * ldc + c);
                v0 += r1.x; v1 += r1.y; v2 += r2.x; v3 += r2.y;
            }
            if (OUTF) {
                float* Cf = (float*)Cg + (long)blockIdx.z * sC;
                *reinterpret_cast<float2*>(Cf + r0 * ldc + c)       = make_float2(v0, v1);
                *reinterpret_cast<float2*>(Cf + (r0 + 8) * ldc + c) = make_float2(v2, v3);
            } else {
                __half* Ch = (__half*)Cg + (long)blockIdx.z * sC;
                *reinterpret_cast<__half2*>(Ch + r0 * ldc + c)       = __floats2half2_rn(v0, v1);
                *reinterpret_cast<__half2*>(Ch + (r0 + 8) * ldc + c) = __floats2half2_rn(v2, v3);
            }
        }
    }
}

// ================= row softmax on fp16 S =================
__global__ void softmax_kernel(__half* __restrict__ S) {
    __half* p = S + (size_t)blockIdx.x * L_DIM;
    int t = threadIdx.x;

    uint4 u[2];
    u[0] = reinterpret_cast<const uint4*>(p)[t];
    u[1] = reinterpret_cast<const uint4*>(p)[t + 256];

    float f[16];
    #pragma unroll
    for (int i = 0; i < 2; i++) {
        const unsigned int* w = reinterpret_cast<const unsigned int*>(&u[i]);
        #pragma unroll
        for (int j = 0; j < 4; j++) {
            float2 ff = __half22float2(*reinterpret_cast<const __half2*>(&w[j]));
            f[i * 8 + j * 2]     = ff.x;
            f[i * 8 + j * 2 + 1] = ff.y;
        }
    }

    float mx = -3.4e38f;
    #pragma unroll
    for (int i = 0; i < 16; i++) mx = fmaxf(mx, f[i]);
    #pragma unroll
    for (int o = 16; o; o >>= 1) mx = fmaxf(mx, __shfl_xor_sync(0xffffffffu, mx, o));

    __shared__ float red[8];
    if ((t & 31) == 0) red[t >> 5] = mx;
    __syncthreads();
    #pragma unroll
    for (int w = 0; w < 8; w++) mx = fmaxf(mx, red[w]);
    __syncthreads();

    float sum = 0.f;
    #pragma unroll
    for (int i = 0; i < 16; i++) {
        f[i] = __expf(f[i] - mx);
        sum += f[i];
    }
    #pragma unroll
    for (int o = 16; o; o >>= 1) sum += __shfl_xor_sync(0xffffffffu, sum, o);
    if ((t & 31) == 0) red[t >> 5] = sum;
    __syncthreads();
    float tot = 0.f;
    #pragma unroll
    for (int w = 0; w < 8; w++) tot += red[w];
    float rinv = 1.0f / tot;

    #pragma unroll
    for (int i = 0; i < 2; i++) {
        unsigned int* w = reinterpret_cast<unsigned int*>(&u[i]);
        #pragma unroll
        for (int j = 0; j < 4; j++) {
            __half2 h2 = __floats2half2_rn(f[i * 8 + j * 2] * rinv,
                                           f[i * 8 + j * 2 + 1] * rinv);
            w[j] = *reinterpret_cast<unsigned int*>(&h2);
        }
    }
    reinterpret_cast<uint4*>(p)[t]       = u[0];
    reinterpret_cast<uint4*>(p)[t + 256] = u[1];
}

// ================= launch =================
extern "C" void kernel_launch(void* const* d_in, const int* in_sizes, int n_in,
                              void* d_out, int out_size) {
    const float* x      = (const float*)d_in[0];
    const float* norm_g = (const float*)d_in[1];
    const float* norm_b = (const float*)d_in[2];
    const float* q_w    = (const float*)d_in[3];
    const float* q_b    = (const float*)d_in[4];
    const float* k_w    = (const float*)d_in[5];
    const float* k_b    = (const float*)d_in[6];
    const float* v_w    = (const float*)d_in[7];
    const float* v_b    = (const float*)d_in[8];
    const float* p_w    = (const float*)d_in[9];
    const float* p_b    = (const float*)d_in[10];
    float* out = (float*)d_out;

    __half *ht, *qk, *v, *h2, *s, *wqk, *wv, *wp;
    float* bqk;
    cudaGetSymbolAddress((void**)&ht,  g_ht);
    cudaGetSymbolAddress((void**)&qk,  g_qk);
    cudaGetSymbolAddress((void**)&v,   g_v);
    cudaGetSymbolAddress((void**)&h2,  g_h2);
    cudaGetSymbolAddress((void**)&s,   g_s);
    cudaGetSymbolAddress((void**)&wqk, g_wqk);
    cudaGetSymbolAddress((void**)&wv,  g_wv);
    cudaGetSymbolAddress((void**)&wp,  g_wp);
    cudaGetSymbolAddress((void**)&bqk, g_bqk);

    const int DSM = 2 * STG_H * 2;   // 73728 B
    cudaFuncSetAttribute(hmma_gemm<2, false, false>, cudaFuncAttributeMaxDynamicSharedMemorySize, DSM);
    cudaFuncSetAttribute(hmma_gemm<1, false, false>, cudaFuncAttributeMaxDynamicSharedMemorySize, DSM);
    cudaFuncSetAttribute(hmma_gemm<0, false, false>, cudaFuncAttributeMaxDynamicSharedMemorySize, DSM);
    cudaFuncSetAttribute(hmma_gemm<1, true,  true >, cudaFuncAttributeMaxDynamicSharedMemorySize, DSM);

    const long SQK = (long)L_DIM * 512;

    // 0) weights -> fp16 (q scaled by 1/16), stacked qk bias
    wconv_kernel<<<C_DIM * C_DIM / 256, 256>>>(q_w, k_w, v_w, p_w, q_b, k_b);

    // 1) group norm -> h_t [L,C] fp16
    gn_kernel<<<B_SZ * N_GROUPS, 256>>>(x, norm_g, norm_b);

    // 2) qk conv: qk[l, 0:512] = h_t[l,:] @ [wq/16 ; wk]^T + [qb/16 ; kb]
    hmma_gemm<2, false, false><<<dim3(4, 32, B_SZ), 256, DSM>>>(
        ht, wqk, bqk, nullptr, qk, C_DIM, C_DIM, C_DIM, 512, 1.0f, CL, 0, 0, SQK);

    //    v[o,l] = sum_c wv[o,c]*h_t[l,c] + vb[o]
    hmma_gemm<1, false, false><<<dim3(32, 2, B_SZ), 256, DSM>>>(
        wv, ht, v_b, nullptr, v, C_DIM, C_DIM, C_DIM, L_DIM, 1.0f, 0, CL, 0, CL);

    // 3) S[i,j] = sum_c qk[i,c]*qk[j,256+c]
    hmma_gemm<0, false, false><<<dim3(32, 32, B_SZ), 256, DSM>>>(
        qk, qk + 256, nullptr, nullptr, s, C_DIM, 512, 512, L_DIM, 1.0f, SQK, SQK, 0, (long)LL);

    // 4) softmax rows
    softmax_kernel<<<B_SZ * L_DIM, 256>>>(s);

    // 5) h2_t[i,c] = sum_j P[i,j]*v[c,j]  -> fp16
    hmma_gemm<0, false, false><<<dim3(2, 32, B_SZ), 256, DSM>>>(
        s, v, nullptr, nullptr, h2, L_DIM, L_DIM, L_DIM, C_DIM, 1.0f, (long)LL, CL, 0, CL);

    // 6) out[o,i] = x[o,i] + sum_c wp[o,c]*h2_t[i,c] + pb[o]
    hmma_gemm<1, true, true><<<dim3(32, 2, B_SZ), 256, DSM>>>(
        wp, h2, p_b, x, out, C_DIM, C_DIM, C_DIM, L_DIM, 1.0f, 0, CL, CL, CL);
}